// round 8
// baseline (speedup 1.0000x reference)
#include <cuda_runtime.h>
#include <cuda_bf16.h>
#include <cstdint>
#include <cstddef>

#define B_   8
#define N_   8192
#define M_   2048
#define CIN  64

// ---- SMEM layout (bytes) ----
// bias 512 f32 | pmax 512 f32 | A u32[128][136] (hi/lo interleaved pairs) | W ping | W pong
#define OFF_BIAS 0
#define OFF_PMAX 2048
#define OFF_A    4096
#define OFF_W0   (OFF_A + 128 * 136 * 4)     // 73728
#define OFF_W1   (OFF_W0 + 128 * 160)        // 94208  (W row = 20 pairs = 160 B)
#define SMEM_BYTES (OFF_W1 + 128 * 160)      // 114688

// pre-converted weights: 15 chunks x [128 n][8 uint4] ; chunk = 32 k
__device__ uint4 g_wpk[15 * 1024];
// transposed features featT[b][n][c]
__device__ float g_featT[(size_t)B_ * N_ * CIN];

__device__ __forceinline__ void bsplit(float v, __nv_bfloat16& h, __nv_bfloat16& l) {
    h = __float2bfloat16(v);
    l = __float2bfloat16(v - __bfloat162float(h));
}
__device__ __forceinline__ uint32_t pk(__nv_bfloat16 a, __nv_bfloat16 b) {
    __nv_bfloat162 t(a, b);
    return *(uint32_t*)&t;
}
// pack 4 consecutive cols -> uint4 {hi01, lo01, hi23, lo23}
__device__ __forceinline__ uint4 pack4(const float* v) {
    __nv_bfloat16 h0,l0,h1,l1,h2,l2,h3,l3;
    bsplit(v[0], h0, l0); bsplit(v[1], h1, l1);
    bsplit(v[2], h2, l2); bsplit(v[3], h3, l3);
    uint4 q;
    q.x = pk(h0, h1); q.y = pk(l0, l1);
    q.z = pk(h2, h3); q.w = pk(l2, l3);
    return q;
}

__device__ __forceinline__ void mma_bf16(float c[4], const uint32_t a[4],
                                         uint32_t b0, uint32_t b1) {
    asm volatile(
        "mma.sync.aligned.m16n8k16.row.col.f32.bf16.bf16.f32 "
        "{%0,%1,%2,%3}, {%4,%5,%6,%7}, {%8,%9}, {%0,%1,%2,%3};"
        : "+f"(c[0]), "+f"(c[1]), "+f"(c[2]), "+f"(c[3])
        : "r"(a[0]), "r"(a[1]), "r"(a[2]), "r"(a[3]), "r"(b0), "r"(b1));
}

__device__ __forceinline__ void cp16(uint32_t smem_dst, const void* gsrc) {
    asm volatile("cp.async.cg.shared.global [%0], [%1], 16;"
                 :: "r"(smem_dst), "l"(gsrc) : "memory");
}
#define CP_COMMIT() asm volatile("cp.async.commit_group;" ::: "memory")
#define CP_WAIT(n)  asm volatile("cp.async.wait_group %0;" :: "n"(n) : "memory")

// One 32-k chunk of the m32 x n64 warp-tile GEMM, 3-pass bf16 compensation.
// A/W hold interleaved {hi,lo} pairs: uint2 load gives both.
template<int KS>
__device__ __forceinline__ void gemm_chunk(const uint32_t* __restrict__ sA,
                                           const uint32_t* __restrict__ sW,
                                           int kbase, int r0, int n0, int lane,
                                           float C[2][8][4])
{
    const int rq = lane >> 2, kq = (lane & 3) * 2;
    #pragma unroll
    for (int ks = 0; ks < KS; ks++) {
        const int ka = kbase + ks * 16 + kq;
        const int kw = ks * 16 + kq;
        uint2 a[2][4];
        #pragma unroll
        for (int mt = 0; mt < 2; mt++) {
            const uint32_t* pA = sA + (r0 + mt * 16 + rq) * 136;
            a[mt][0] = *(const uint2*)(pA + ka);
            a[mt][1] = *(const uint2*)(pA + 8 * 136 + ka);
            a[mt][2] = *(const uint2*)(pA + ka + 8);
            a[mt][3] = *(const uint2*)(pA + 8 * 136 + ka + 8);
        }
        uint32_t ahi[2][4], alo[2][4];
        #pragma unroll
        for (int mt = 0; mt < 2; mt++)
            #pragma unroll
            for (int i = 0; i < 4; i++) {
                ahi[mt][i] = a[mt][i].x;
                alo[mt][i] = a[mt][i].y;
            }
        #pragma unroll
        for (int j = 0; j < 8; j++) {
            const uint32_t* pW = sW + (n0 + j * 8 + rq) * 40;
            uint2 w0 = *(const uint2*)(pW + kw);
            uint2 w1 = *(const uint2*)(pW + kw + 8);
            mma_bf16(C[0][j], ahi[0], w0.x, w1.x);   // hi*hi
            mma_bf16(C[1][j], ahi[1], w0.x, w1.x);
            mma_bf16(C[0][j], ahi[0], w0.y, w1.y);   // hi*lo
            mma_bf16(C[1][j], ahi[1], w0.y, w1.y);
            mma_bf16(C[0][j], alo[0], w0.x, w1.x);   // lo*hi
            mma_bf16(C[1][j], alo[1], w0.x, w1.x);
        }
    }
}

__device__ __forceinline__ void zeroC(float C[2][8][4]) {
    #pragma unroll
    for (int mt = 0; mt < 2; mt++)
        #pragma unroll
        for (int j = 0; j < 8; j++)
            #pragma unroll
            for (int x = 0; x < 4; x++) C[mt][j][x] = 0.f;
}

// bias+relu -> interleaved bf16 hi/lo pairs back into A
__device__ __forceinline__ void epi(const float C[2][8][4], const float* __restrict__ bias,
                                    int r0, int n0, int lane, uint32_t* __restrict__ sA)
{
    const int rq = lane >> 2, q2 = (lane & 3) * 2;
    #pragma unroll
    for (int mt = 0; mt < 2; mt++) {
        const int ra = r0 + mt * 16 + rq;
        #pragma unroll
        for (int j = 0; j < 8; j++) {
            const int c0 = n0 + j * 8 + q2;
            const float bb0 = bias[c0], bb1 = bias[c0 + 1];
            float v0 = fmaxf(C[mt][j][0] + bb0, 0.f);
            float v1 = fmaxf(C[mt][j][1] + bb1, 0.f);
            float v2 = fmaxf(C[mt][j][2] + bb0, 0.f);
            float v3 = fmaxf(C[mt][j][3] + bb1, 0.f);
            __nv_bfloat16 h0,l0,h1,l1;
            uint2 p;
            bsplit(v0, h0, l0); bsplit(v1, h1, l1);
            p.x = pk(h0, h1); p.y = pk(l0, l1);
            *(uint2*)(sA + ra * 136 + c0) = p;
            bsplit(v2, h0, l0); bsplit(v3, h1, l1);
            p.x = pk(h0, h1); p.y = pk(l0, l1);
            *(uint2*)(sA + (ra + 8) * 136 + c0) = p;
        }
    }
}

// ---------------- prep: convert W1/W2/W3 -> g_wpk chunks ----------------
__global__ __launch_bounds__(256) void prep_kernel(const float* __restrict__ W1,
                                                   const float* __restrict__ W2,
                                                   const float* __restrict__ W3)
{
    const int c = blockIdx.x, tid = threadIdx.x;
    const float* W; int ld, coloff, kreal, kbase;
    if (c < 3)       { W = W1; ld = 128; coloff = 0;   kreal = 67;  kbase = c * 32; }
    else if (c < 7)  { W = W2; ld = 128; coloff = 0;   kreal = 128; kbase = (c - 3) * 32; }
    else if (c < 11) { W = W3; ld = 256; coloff = 0;   kreal = 128; kbase = (c - 7) * 32; }
    else             { W = W3; ld = 256; coloff = 128; kreal = 128; kbase = (c - 11) * 32; }
    #pragma unroll
    for (int i = 0; i < 4; i++) {
        const int g = tid + (i << 8);
        const int n = g >> 3, pp = g & 7;
        const int k0 = kbase + pp * 4;
        float v[4];
        #pragma unroll
        for (int j = 0; j < 4; j++) {
            const int k = k0 + j;
            v[j] = (k < kreal) ? W[(size_t)k * ld + coloff + n] : 0.f;
        }
        g_wpk[(size_t)c * 1024 + g] = pack4(v);
    }
}

// ---------------- feature transpose [C][N] -> [N][C] ----------------
__global__ __launch_bounds__(256) void tr_kernel(const float* __restrict__ feat) {
    __shared__ float t[64][65];
    const int b  = blockIdx.x >> 7;
    const int n0 = (blockIdx.x & 127) << 6;
    const int tid = threadIdx.x;
    const float* fb = feat + (size_t)b * CIN * N_;
    for (int i = tid; i < 64 * 64; i += 256) {
        int c = i >> 6, nj = i & 63;
        t[c][nj] = fb[(size_t)c * N_ + n0 + nj];
    }
    __syncthreads();
    const int nj = tid >> 2, cq = (tid & 3) * 16;
    float* drow = g_featT + ((size_t)b * N_ + n0 + nj) * CIN + cq;
    #pragma unroll
    for (int q = 0; q < 16; q += 4) {
        float4 v = make_float4(t[cq + q][nj], t[cq + q + 1][nj],
                               t[cq + q + 2][nj], t[cq + q + 3][nj]);
        *(float4*)(drow + q) = v;
    }
}

// ---------------- main: 128 rows / 4 neighborhoods per CTA, 2 CTAs/SM ----------------
__global__ __launch_bounds__(256, 2)
void ps_mma4(const float* __restrict__ xyz,
             const int* __restrict__ nbr, const int* __restrict__ anc,
             const float* __restrict__ b1, const float* __restrict__ b2,
             const float* __restrict__ b3, float* __restrict__ out)
{
    extern __shared__ char smem[];
    float* bias = (float*)(smem + OFF_BIAS);
    float* pmax = (float*)(smem + OFF_PMAX);
    uint32_t* sA = (uint32_t*)(smem + OFF_A);
    const uint32_t sbase = (uint32_t)__cvta_generic_to_shared(smem);

    const int tid = threadIdx.x, lane = tid & 31, w = tid >> 5;
    const int ct = blockIdx.x, b = ct >> 9;
    const int m0 = (ct & 511) << 2;

    // stream chunk c into buf[c&1] via cp.async (no regs, no converts)
    auto stage = [&](int c) {
        const char* src = (const char*)g_wpk + (size_t)c * 16384;
        const uint32_t wb = sbase + ((c & 1) ? OFF_W1 : OFF_W0);
        #pragma unroll
        for (int i = 0; i < 4; i++) {
            const int g = tid + (i << 8);
            cp16(wb + (g >> 3) * 160 + (g & 7) * 16, src + (size_t)g * 16);
        }
        CP_COMMIT();
    };
    const uint32_t* wbuf[2] = {(const uint32_t*)(smem + OFF_W0),
                               (const uint32_t*)(smem + OFF_W1)};

    stage(0);

    for (int i = tid; i < 512; i += 256)
        bias[i] = (i < 128) ? b1[i] : (i < 256) ? b2[i - 128] : b3[i - 256];

    // ---- gather rows [128][80] = [rel_xyz(3)|feat(64)|0..] while chunk0 streams ----
    {
        const int r = tid >> 1, h = tid & 1;
        const int m = m0 + (r >> 5), k = r & 31;
        const int n = nbr[(b * M_ + m) * 32 + k];
        const int a = anc[b * M_ + m];
        const float* xb = xyz + (size_t)b * N_ * 3;
        const float* ft = g_featT + ((size_t)b * N_ + n) * CIN;
        float xr[3];
        if (h == 0) {
            xr[0] = xb[n * 3 + 0] - xb[a * 3 + 0];
            xr[1] = xb[n * 3 + 1] - xb[a * 3 + 1];
            xr[2] = xb[n * 3 + 2] - xb[a * 3 + 2];
        }
        #pragma unroll 1
        for (int cb = h * 4; cb < 80; cb += 8) {
            float v[4];
            #pragma unroll
            for (int j = 0; j < 4; j++) {
                const int c = cb + j;
                v[j] = (c < 3) ? xr[c] : (c < 67) ? __ldg(ft + (c - 3)) : 0.f;
            }
            *(uint4*)(sA + r * 136 + cb) = pack4(v);
        }
    }

    const int rg = w & 3;
    const int r0 = rg * 32;
    const int n0 = (w >> 2) * 64;
    float C[2][8][4];

    // chunk stream: 0-2 = L1 (k-steps 2,2,1), 3-6 = L2, 7-10 = L3h0, 11-14 = L3h1
    // ---- layer 1 ----
    stage(1); CP_WAIT(1); __syncthreads();
    zeroC(C);
    gemm_chunk<2>(sA, wbuf[0], 0, r0, n0, lane, C);
    __syncthreads();
    stage(2); CP_WAIT(1); __syncthreads();
    gemm_chunk<2>(sA, wbuf[1], 32, r0, n0, lane, C);
    __syncthreads();
    stage(3); CP_WAIT(1); __syncthreads();
    gemm_chunk<1>(sA, wbuf[0], 64, r0, n0, lane, C);
    __syncthreads();
    epi(C, bias, r0, n0, lane, sA);

    // ---- layer 2 ----
    stage(4); CP_WAIT(1); __syncthreads();
    zeroC(C);
    gemm_chunk<2>(sA, wbuf[1], 0, r0, n0, lane, C);
    __syncthreads();
    stage(5); CP_WAIT(1); __syncthreads();
    gemm_chunk<2>(sA, wbuf[0], 32, r0, n0, lane, C);
    __syncthreads();
    stage(6); CP_WAIT(1); __syncthreads();
    gemm_chunk<2>(sA, wbuf[1], 64, r0, n0, lane, C);
    __syncthreads();
    stage(7); CP_WAIT(1); __syncthreads();
    gemm_chunk<2>(sA, wbuf[0], 96, r0, n0, lane, C);
    __syncthreads();
    epi(C, bias + 128, r0, n0, lane, sA);

    // ---- layer 3: two col halves + in-warp maxpool ----
    #pragma unroll 1
    for (int h3 = 0; h3 < 2; h3++) {
        const int cb0 = 7 + h3 * 4;        // first chunk of this half (already resident at entry)
        zeroC(C);
        #pragma unroll 1
        for (int q = 0; q < 4; q++) {
            const int c = cb0 + q;
            if (q > 0) __syncthreads();    // readers of buf[(c)&1] from prior gemm done
            if (c + 1 < 15) { stage(c + 1); CP_WAIT(1); } else { CP_WAIT(0); }
            __syncthreads();
            gemm_chunk<2>(sA, wbuf[c & 1], q * 32, r0, n0, lane, C);
        }

        const int q2 = (lane & 3) * 2;
        #pragma unroll
        for (int j = 0; j < 8; j++) {
            const int c0 = n0 + j * 8 + q2;
            const float bb0 = bias[256 + h3 * 128 + c0];
            const float bb1 = bias[256 + h3 * 128 + c0 + 1];
            float v0 = fmaxf(fmaxf(C[0][j][0], C[0][j][2]),
                             fmaxf(C[1][j][0], C[1][j][2]));
            float v1 = fmaxf(fmaxf(C[0][j][1], C[0][j][3]),
                             fmaxf(C[1][j][1], C[1][j][3]));
            v0 = fmaxf(v0 + bb0, 0.f);
            v1 = fmaxf(v1 + bb1, 0.f);
            #pragma unroll
            for (int s = 4; s < 32; s <<= 1) {
                v0 = fmaxf(v0, __shfl_xor_sync(0xFFFFFFFFu, v0, s));
                v1 = fmaxf(v1, __shfl_xor_sync(0xFFFFFFFFu, v1, s));
            }
            if (lane < 4) {
                pmax[rg * 128 + c0]     = v0;
                pmax[rg * 128 + c0 + 1] = v1;
            }
        }
        __syncthreads();
        if (tid < 128) {
            const int col = tid;
            float4 f = make_float4(pmax[0 * 128 + col], pmax[1 * 128 + col],
                                   pmax[2 * 128 + col], pmax[3 * 128 + col]);
            *(float4*)(out + ((size_t)(b * 256 + h3 * 128 + col)) * M_ + m0) = f;
        }
        __syncthreads();
    }
}

extern "C" void kernel_launch(void* const* d_in, const int* in_sizes, int n_in,
                              void* d_out, int out_size)
{
    const float* xyz  = (const float*)d_in[0];
    const float* feat = (const float*)d_in[1];
    const int*   nbr  = (const int*)d_in[2];
    const int*   anc  = (const int*)d_in[3];
    const float* W1   = (const float*)d_in[4];
    const float* b1   = (const float*)d_in[5];
    const float* W2   = (const float*)d_in[6];
    const float* b2   = (const float*)d_in[7];
    const float* W3   = (const float*)d_in[8];
    const float* b3   = (const float*)d_in[9];
    float* out = (float*)d_out;

    prep_kernel<<<15, 256>>>(W1, W2, W3);
    tr_kernel<<<B_ * (N_ / 64), 256>>>(feat);
    cudaFuncSetAttribute(ps_mma4, cudaFuncAttributeMaxDynamicSharedMemorySize, SMEM_BYTES);
    ps_mma4<<<4096, 256, SMEM_BYTES>>>(xyz, nbr, anc, b1, b2, b3, out);
}